// round 13
// baseline (speedup 1.0000x reference)
#include <cuda_runtime.h>
#include <cuda_bf16.h>
#include <cuda_fp16.h>
#include <math.h>
#include <stdint.h>

#define BB 64
#define NN 1024
#define SS 64
#define DD 768
#define HH 256
#define KEEP 96
#define CAND 128
#define MM (BB*NN)

// ---------------- device scratch (no allocations allowed) ----------------
__device__ float          g_ctxh[BB*HH];
__device__ float          g_scoresA[MM];
__device__ int            g_cand[BB*CAND];
__device__ int            g_topk[BB*KEEP];
__device__ float          g_rpart[2][BB*CAND];
__device__ __nv_bfloat16  g_Bhi[HH*DD];    // refine: W1 visual, [h][d], bf16 hi
__device__ __nv_bfloat16  g_Blo[HH*DD];    // refine: bf16 lo residual
__device__ __half         g_Bh16[HH*DD];   // approx: W1 visual, [h][d], fp16

// ---------------- PTX helpers ----------------
__device__ __forceinline__ uint32_t smem_u32(const void* p) {
    uint32_t a;
    asm("{ .reg .u64 t; cvta.to.shared.u64 t, %1; cvt.u32.u64 %0, t; }" : "=r"(a) : "l"(p));
    return a;
}
__device__ __forceinline__ void ldsm4(uint32_t* r, uint32_t addr) {
    asm volatile("ldmatrix.sync.aligned.m8n8.x4.shared.b16 {%0,%1,%2,%3}, [%4];"
                 : "=r"(r[0]), "=r"(r[1]), "=r"(r[2]), "=r"(r[3]) : "r"(addr));
}
__device__ __forceinline__ void mma_bf16(float* d, const uint32_t* a, const uint32_t* b) {
    asm volatile(
        "mma.sync.aligned.m16n8k16.row.col.f32.bf16.bf16.f32 "
        "{%0,%1,%2,%3}, {%4,%5,%6,%7}, {%8,%9}, {%0,%1,%2,%3};"
        : "+f"(d[0]), "+f"(d[1]), "+f"(d[2]), "+f"(d[3])
        : "r"(a[0]), "r"(a[1]), "r"(a[2]), "r"(a[3]), "r"(b[0]), "r"(b[1]));
}
// fp16 inputs, fp16 accumulate (packed f16x2 x2)
__device__ __forceinline__ void mma_f16acc(uint32_t* d, const uint32_t* a, const uint32_t* b) {
    asm volatile(
        "mma.sync.aligned.m16n8k16.row.col.f16.f16.f16.f16 "
        "{%0,%1}, {%2,%3,%4,%5}, {%6,%7}, {%0,%1};"
        : "+r"(d[0]), "+r"(d[1])
        : "r"(a[0]), "r"(a[1]), "r"(a[2]), "r"(a[3]), "r"(b[0]), "r"(b[1]));
}
__device__ __forceinline__ void cpasync16(uint32_t dst, const void* src) {
    asm volatile("cp.async.ca.shared.global [%0], [%1], 16;" :: "r"(dst), "l"(src));
}
__device__ __forceinline__ void cpasync_commit() { asm volatile("cp.async.commit_group;"); }
__device__ __forceinline__ void cpasync_wait0()  { asm volatile("cp.async.wait_group 0;"); }

__device__ __forceinline__ void split_bf16(float x, uint32_t& hi_us, uint32_t& lo_us) {
    __nv_bfloat16 h = __float2bfloat16_rn(x);
    float r = x - __bfloat162float(h);
    __nv_bfloat16 l = __float2bfloat16_rn(r);
    hi_us = (uint32_t)__bfloat16_as_ushort(h);
    lo_us = (uint32_t)__bfloat16_as_ushort(l);
}
__device__ __forceinline__ uint32_t f2_to_h2(float x, float y) {
    __half2 h = __floats2half2_rn(x, y);
    return *(uint32_t*)&h;
}

// ---------------- Kernel 0: fused prep (W1 splits) + ctx ----------------
__global__ __launch_bounds__(256) void prepare_kernel(
    const float* __restrict__ W1, const float* __restrict__ text,
    const float* __restrict__ b1)
{
    if (blockIdx.x < DD * HH / 256) {
        int e = blockIdx.x * 256 + threadIdx.x;
        int d = e >> 8, h = e & 255;
        float x = W1[(size_t)d * HH + h];
        uint32_t hi, lo; split_bf16(x, hi, lo);
        g_Bhi[h * DD + d] = __ushort_as_bfloat16((unsigned short)hi);
        g_Blo[h * DD + d] = __ushort_as_bfloat16((unsigned short)lo);
        g_Bh16[h * DD + d] = __float2half_rn(x);
        return;
    }
    __shared__ float tm[DD];
    int b = blockIdx.x - DD * HH / 256, tid = threadIdx.x;
    for (int d = tid; d < DD; d += 256) {
        const float* p = text + (size_t)b * SS * DD + d;
        float s = 0.f;
        #pragma unroll 8
        for (int j = 0; j < SS; ++j) s += p[(size_t)j * DD];
        tm[d] = s * (1.0f / SS);
    }
    __syncthreads();
    int h = tid;
    float acc = b1[h];
    const float* w = W1 + (size_t)DD * HH + h;
    #pragma unroll 8
    for (int d = 0; d < DD; ++d) acc += tm[d] * w[(size_t)d * HH];
    g_ctxh[b * HH + h] = acc;
}

// ================= Approx scorer v2: fp16/f16acc, M-tile 128, warp tile 64x64 =================
// Block 256 thr (8 warps 2Mx4N), tile M=128 x N=256, K-chunks 64, 12 chunks.
// A single-buffered (reloaded per chunk), B double-buffered via cp.async.
// B L2 traffic halved vs M=64 tiles; 8 LDSM -> 32 MMA per kk.
#define SA_A      0u                                  // 128*144 = 18432
#define SA_B(buf) ((uint32_t)(18432 + (buf)*36864))   // 256*144 each
#define SA_CTX 92160u
#define SA_W2  93184u
#define SA_PART 94208u                                // 128*4*4 = 2048
#define SA_BYTES 96256u

__global__ __launch_bounds__(256, 2) void scorer_approx(
    const float* __restrict__ dv, const float* __restrict__ W2,
    const float* __restrict__ b2p)
{
    extern __shared__ char smem[];
    uint32_t sb = smem_u32(smem);
    const int tid = threadIdx.x, wid = tid >> 5, lane = tid & 31;
    const int warpM = wid >> 2, warpN = wid & 3;      // 2 x 4
    const int row0 = blockIdx.x * 128;
    const int b = blockIdx.x >> 3;                    // 8 blocks per batch

    ((float*)(smem + SA_CTX))[tid] = g_ctxh[b * HH + tid];
    ((float*)(smem + SA_W2))[tid]  = W2[tid];

    uint32_t acc2[4][8][2];                           // [mt][nt*2+h][2]
    #pragma unroll
    for (int m = 0; m < 4; ++m)
        #pragma unroll
        for (int j = 0; j < 8; ++j) { acc2[m][j][0] = 0u; acc2[m][j][1] = 0u; }

    const uint32_t a_row_l = (uint32_t)(lane & 15);
    const uint32_t a_k_l   = (uint32_t)(lane >> 4) * 16u;
    const uint32_t b_n_l   = (uint32_t)((lane & 7) + ((lane >> 4) << 3));
    const uint32_t b_k_l   = (uint32_t)((lane >> 3) & 1) * 16u;

    // A loader: 2048 float4 units per chunk (128 rows x 16 quads), 8/thread
    const int ar = tid >> 4, aq = tid & 15;

    // chunk 0: A + B
    {
        #pragma unroll 4
        for (int i = 0; i < 8; ++i) {
            int r = ar + i * 16;
            float4 v = *(const float4*)(dv + (size_t)(row0 + r) * DD + aq * 4);
            uint2 hv = { f2_to_h2(v.x, v.y), f2_to_h2(v.z, v.w) };
            *(uint2*)(smem + SA_A + r * 144 + aq * 8) = hv;
        }
        #pragma unroll
        for (int i = 0; i < 8; ++i) {
            int idx = i * 256 + tid;                  // 2048 units: 256 rows x 8 x 16B
            int n = idx >> 3, q = idx & 7;
            cpasync16(sb + SA_B(0) + n*144 + q*16, g_Bh16 + (size_t)n * DD + q * 8);
        }
        cpasync_commit();
        cpasync_wait0();
    }
    __syncthreads();

    for (int c = 0; c < 12; ++c) {
        const int cur = c & 1;
        if (c < 11) {
            const int k0 = (c + 1) * 64;
            #pragma unroll
            for (int i = 0; i < 8; ++i) {
                int idx = i * 256 + tid;
                int n = idx >> 3, q = idx & 7;
                cpasync16(sb + SA_B(cur ^ 1) + n*144 + q*16, g_Bh16 + (size_t)n * DD + k0 + q * 8);
            }
            cpasync_commit();
        }

        const uint32_t Bh = sb + SA_B(cur);
        #pragma unroll
        for (int kk = 0; kk < 4; ++kk) {
            const uint32_t kb = (uint32_t)(kk * 32);
            uint32_t ah[4][4];
            #pragma unroll
            for (int mt = 0; mt < 4; ++mt)
                ldsm4(ah[mt], sb + SA_A + (uint32_t)(warpM*64 + mt*16 + a_row_l)*144 + kb + a_k_l);
            #pragma unroll
            for (int nt = 0; nt < 4; ++nt) {
                uint32_t bh[4];
                ldsm4(bh, Bh + (uint32_t)(warpN*64 + nt*16 + b_n_l)*144 + kb + b_k_l);
                #pragma unroll
                for (int mt = 0; mt < 4; ++mt) {
                    mma_f16acc(acc2[mt][nt*2],   ah[mt], bh);
                    mma_f16acc(acc2[mt][nt*2+1], ah[mt], bh+2);
                }
            }
        }

        if (c < 11) {
            const int k0 = (c + 1) * 64;
            __syncthreads();                          // all warps done reading A
            #pragma unroll 4
            for (int i = 0; i < 8; ++i) {
                int r = ar + i * 16;
                float4 v = *(const float4*)(dv + (size_t)(row0 + r) * DD + k0 + aq * 4);
                uint2 hv = { f2_to_h2(v.x, v.y), f2_to_h2(v.z, v.w) };
                *(uint2*)(smem + SA_A + r * 144 + aq * 8) = hv;
            }
            cpasync_wait0();
            __syncthreads();
        }
    }

    // epilogue: unpack f16 accum -> f32, +ctx, relu, dot W2
    const float* sctx = (const float*)(smem + SA_CTX);
    const float* sw2  = (const float*)(smem + SA_W2);
    float* part = (float*)(smem + SA_PART);           // [128][4]
    #pragma unroll
    for (int mt = 0; mt < 4; ++mt) {
        float lg0 = 0.f, lg1 = 0.f;
        #pragma unroll
        for (int j = 0; j < 8; ++j) {
            int n = warpN*64 + j*8 + (lane & 3)*2;
            float c0 = sctx[n], c1 = sctx[n+1], w0 = sw2[n], w1 = sw2[n+1];
            float2 f01 = __half22float2(*(__half2*)&acc2[mt][j][0]);
            float2 f23 = __half22float2(*(__half2*)&acc2[mt][j][1]);
            lg0 += fmaxf(f01.x + c0, 0.f) * w0 + fmaxf(f01.y + c1, 0.f) * w1;
            lg1 += fmaxf(f23.x + c0, 0.f) * w0 + fmaxf(f23.y + c1, 0.f) * w1;
        }
        lg0 += __shfl_xor_sync(0xffffffffu, lg0, 1);
        lg0 += __shfl_xor_sync(0xffffffffu, lg0, 2);
        lg1 += __shfl_xor_sync(0xffffffffu, lg1, 1);
        lg1 += __shfl_xor_sync(0xffffffffu, lg1, 2);
        if ((lane & 3) == 0) {
            int r0 = warpM*64 + mt*16 + (lane >> 2);
            part[r0 * 4 + warpN]       = lg0;
            part[(r0 + 8) * 4 + warpN] = lg1;
        }
    }
    __syncthreads();
    if (tid < 128)
        g_scoresA[row0 + tid] = part[tid*4] + part[tid*4+1] + part[tid*4+2] + part[tid*4+3] + b2p[0];
}

// ---------------- approx top-128: 16-bit binary search ----------------
__global__ __launch_bounds__(1024) void topk128_kernel()
{
    __shared__ int weq[32], wsel[32];
    int b = blockIdx.x, i = threadIdx.x;
    int lane = i & 31, warp = i >> 5;
    unsigned bits = __float_as_uint(g_scoresA[b * NN + i]);
    unsigned ui = (bits & 0x80000000u) ? ~bits : (bits | 0x80000000u);
    ui &= 0xFFFF0000u;                    // coarse 16-bit key; ties -> index order

    unsigned thr = 0;
    #pragma unroll
    for (int bit = 31; bit >= 16; --bit) {
        unsigned trial = thr | (1u << bit);
        int c = __syncthreads_count(ui >= trial);
        if (c >= CAND) thr = trial;
    }
    int isGT = ui > thr;
    int isEQ = (ui == thr);
    int cntGT = __syncthreads_count(isGT);
    int k2 = CAND - cntGT;

    unsigned lmlt = (lane == 0) ? 0u : (0xffffffffu >> (32 - lane));
    unsigned eqm = __ballot_sync(0xffffffffu, isEQ);
    if (lane == 0) weq[warp] = __popc(eqm);
    __syncthreads();
    int eqBefore = __popc(eqm & lmlt);
    #pragma unroll
    for (int w = 0; w < 32; ++w) if (w < warp) eqBefore += weq[w];

    int flag = isGT || (isEQ && eqBefore < k2);
    unsigned sm_ = __ballot_sync(0xffffffffu, flag);
    if (lane == 0) wsel[warp] = __popc(sm_);
    __syncthreads();
    int pos = __popc(sm_ & lmlt);
    #pragma unroll
    for (int w = 0; w < 32; ++w) if (w < warp) pos += wsel[w];

    if (flag) g_cand[b * CAND + pos] = i;
}

// ================= Refine: 3-term bf16, 256 thr, 8 warps 2Mx4N, warp tile 32x32 =================
// (R10 configuration: K-chunk 32, pitch 80 — best measured: 36.5 us)
#define RF_A(buf, term) ((uint32_t)(((buf)*2 + (term)) * 5120))
#define RF_B(buf, term) ((uint32_t)(20480 + ((buf)*2 + (term)) * 10240))
#define RF_CTX  61440u
#define RF_W2   61952u
#define RF_PART 62464u
#define RF_BYTES 63488u

__global__ __launch_bounds__(256, 2) void refine_mma(
    const float* __restrict__ dv, const float* __restrict__ W2)
{
    extern __shared__ char smem[];
    uint32_t sb = smem_u32(smem);
    const int tid = threadIdx.x, wid = tid >> 5, lane = tid & 31;
    const int warpM = wid >> 2, warpN = wid & 3;
    const int batch = blockIdx.x >> 2;
    const int half  = (blockIdx.x >> 1) & 1;
    const int nHalf = blockIdx.x & 1;

    if (tid < 128) {
        ((float*)(smem + RF_CTX))[tid] = g_ctxh[batch * HH + nHalf * 128 + tid];
        ((float*)(smem + RF_W2))[tid]  = W2[nHalf * 128 + tid];
    }

    float acc[2][4][4];
    #pragma unroll
    for (int m = 0; m < 2; ++m)
        #pragma unroll
        for (int j = 0; j < 4; ++j)
            #pragma unroll
            for (int r = 0; r < 4; ++r) acc[m][j][r] = 0.f;

    const uint32_t a_row_l = (uint32_t)(lane & 15);
    const uint32_t a_k_l   = (uint32_t)(lane >> 4) * 16u;
    const uint32_t b_n_l   = (uint32_t)((lane & 7) + ((lane >> 4) << 3));
    const uint32_t b_k_l   = (uint32_t)((lane >> 3) & 1) * 16u;

    const int ar0 = tid >> 3, aq0 = tid & 7;
    const int ar1 = (tid + 256) >> 3, aq1 = tid & 7;
    const int crow0 = g_cand[batch * CAND + half * 64 + ar0];
    const int crow1 = g_cand[batch * CAND + half * 64 + ar1];
    const float* aG0 = dv + ((size_t)batch * NN + crow0) * DD + aq0 * 4;
    const float* aG1 = dv + ((size_t)batch * NN + crow1) * DD + aq1 * 4;
    const uint32_t aSt0 = (uint32_t)(ar0 * 80 + aq0 * 8);
    const uint32_t aSt1 = (uint32_t)(ar1 * 80 + aq1 * 8);
    const __nv_bfloat16* BsrcH = g_Bhi + (size_t)nHalf * 128 * DD;
    const __nv_bfloat16* BsrcL = g_Blo + (size_t)nHalf * 128 * DD;

    {
        #pragma unroll
        for (int u = 0; u < 2; ++u) {
            float4 v = u ? *(const float4*)aG1 : *(const float4*)aG0;
            uint32_t h0,h1,h2,h3,l0,l1,l2,l3;
            split_bf16(v.x,h0,l0); split_bf16(v.y,h1,l1);
            split_bf16(v.z,h2,l2); split_bf16(v.w,h3,l3);
            uint2 hv = { h0 | (h1<<16), h2 | (h3<<16) };
            uint2 lv = { l0 | (l1<<16), l2 | (l3<<16) };
            uint32_t st = u ? aSt1 : aSt0;
            *(uint2*)(smem + RF_A(0,0) + st) = hv;
            *(uint2*)(smem + RF_A(0,1) + st) = lv;
        }
        #pragma unroll
        for (int i = 0; i < 4; ++i) {
            int idx = i * 256 + tid;
            int kq = idx & 3, n = (idx >> 2) & 127, term = idx >> 9;
            const __nv_bfloat16* src = (term ? BsrcL : BsrcH) + (size_t)n * DD + kq * 8;
            cpasync16(sb + RF_B(0, term) + n*80 + kq*16, src);
        }
        cpasync_commit();
        cpasync_wait0();
    }
    __syncthreads();

    for (int c = 0; c < 24; ++c) {
        const int cur = c & 1, nxt = cur ^ 1;
        float4 v0, v1;
        if (c < 23) {
            const int k0 = (c + 1) * 32;
            #pragma unroll
            for (int i = 0; i < 4; ++i) {
                int idx = i * 256 + tid;
                int kq = idx & 3, n = (idx >> 2) & 127, term = idx >> 9;
                const __nv_bfloat16* src = (term ? BsrcL : BsrcH) + (size_t)n * DD + k0 + kq * 8;
                cpasync16(sb + RF_B(nxt, term) + n*80 + kq*16, src);
            }
            cpasync_commit();
            v0 = *(const float4*)(aG0 + k0);
            v1 = *(const float4*)(aG1 + k0);
        }

        const uint32_t Ah = sb + RF_A(cur,0), Al = sb + RF_A(cur,1);
        const uint32_t Bh = sb + RF_B(cur,0), Bl = sb + RF_B(cur,1);
        #pragma unroll
        for (int kk = 0; kk < 2; ++kk) {
            const uint32_t kb = (uint32_t)(kk * 32);
            uint32_t ah[2][4], al[2][4];
            #pragma unroll
            for (int mt = 0; mt < 2; ++mt) {
                const uint32_t aoff = (uint32_t)(warpM*32 + mt*16 + a_row_l)*80 + kb + a_k_l;
                ldsm4(ah[mt], Ah + aoff);
                ldsm4(al[mt], Al + aoff);
            }
            #pragma unroll
            for (int nt = 0; nt < 2; ++nt) {
                uint32_t bh[4], bl[4];
                const uint32_t boff = (uint32_t)(warpN*32 + nt*16 + b_n_l)*80 + kb + b_k_l;
                ldsm4(bh, Bh + boff);
                ldsm4(bl, Bl + boff);
                #pragma unroll
                for (int mt = 0; mt < 2; ++mt) {
                    float* d0 = acc[mt][nt*2], *d1 = acc[mt][nt*2+1];
                    mma_bf16(d0, ah[mt], bh);   mma_bf16(d1, ah[mt], bh+2);
                    mma_bf16(d0, ah[mt], bl);   mma_bf16(d1, ah[mt], bl+2);
                    mma_bf16(d0, al[mt], bh);   mma_bf16(d1, al[mt], bh+2);
                }
            }
        }

        if (c < 23) {
            #pragma unroll
            for (int u = 0; u < 2; ++u) {
                float4 v = u ? v1 : v0;
                uint32_t h0,h1,h2,h3,l0,l1,l2,l3;
                split_bf16(v.x,h0,l0); split_bf16(v.y,h1,l1);
                split_bf16(v.z,h2,l2); split_bf16(v.w,h3,l3);
                uint2 hv = { h0 | (h1<<16), h2 | (h3<<16) };
                uint2 lv = { l0 | (l1<<16), l2 | (l3<<16) };
                uint32_t st = u ? aSt1 : aSt0;
                *(uint2*)(smem + RF_A(nxt,0) + st) = hv;
                *(uint2*)(smem + RF_A(nxt,1) + st) = lv;
            }
            cpasync_wait0();
        }
        __syncthreads();
    }

    const float* sctx = (const float*)(smem + RF_CTX);
    const float* sw2  = (const float*)(smem + RF_W2);
    float* part = (float*)(smem + RF_PART);
    #pragma unroll
    for (int mt = 0; mt < 2; ++mt) {
        float lg0 = 0.f, lg1 = 0.f;
        #pragma unroll
        for (int j = 0; j < 4; ++j) {
            int cl = warpN*32 + j*8 + (lane & 3)*2;
            float c0 = sctx[cl], c1 = sctx[cl+1], w0 = sw2[cl], w1 = sw2[cl+1];
            lg0 += fmaxf(acc[mt][j][0] + c0, 0.f) * w0 + fmaxf(acc[mt][j][1] + c1, 0.f) * w1;
            lg1 += fmaxf(acc[mt][j][2] + c0, 0.f) * w0 + fmaxf(acc[mt][j][3] + c1, 0.f) * w1;
        }
        lg0 += __shfl_xor_sync(0xffffffffu, lg0, 1);
        lg0 += __shfl_xor_sync(0xffffffffu, lg0, 2);
        lg1 += __shfl_xor_sync(0xffffffffu, lg1, 1);
        lg1 += __shfl_xor_sync(0xffffffffu, lg1, 2);
        if ((lane & 3) == 0) {
            int r0 = warpM*32 + mt*16 + (lane >> 2);
            part[r0 * 4 + warpN]       = lg0;
            part[(r0 + 8) * 4 + warpN] = lg1;
        }
    }
    __syncthreads();
    if (tid < 64)
        g_rpart[nHalf][batch * CAND + half * 64 + tid] =
            part[tid*4] + part[tid*4+1] + part[tid*4+2] + part[tid*4+3];
}

// ---------------- select: exact top-96 among 128 candidates ----------------
__global__ __launch_bounds__(128) void select_kernel(
    const float* __restrict__ b2p, float* outIdxF, int writeIdx)
{
    __shared__ float sc[CAND];
    __shared__ int wsel[4];
    const int b = blockIdx.x, tid = threadIdx.x, warp = tid >> 5, lane = tid & 31;
    float lg = g_rpart[0][b * CAND + tid] + g_rpart[1][b * CAND + tid] + b2p[0];
    sc[tid] = 1.f / (1.f + expf(-lg));
    __syncthreads();

    float my = sc[tid];
    int rank = 0;
    #pragma unroll 4
    for (int j = 0; j < CAND; ++j) {
        float sj = sc[j];
        rank += (sj > my) || (sj == my && j < tid);
    }
    int flag = (rank < KEEP);
    unsigned m = __ballot_sync(0xffffffffu, flag);
    if (lane == 0) wsel[warp] = __popc(m);
    __syncthreads();
    if (flag) {
        unsigned lmlt = (lane == 0) ? 0u : (0xffffffffu >> (32 - lane));
        int pos = __popc(m & lmlt);
        #pragma unroll
        for (int w = 0; w < 4; ++w) if (w < warp) pos += wsel[w];
        int orig = g_cand[b * CAND + tid];
        g_topk[b * KEEP + pos] = orig;
        if (writeIdx) outIdxF[b * KEEP + pos] = (float)orig;
    }
}

// ---------------- gather: 4 rows per block ----------------
__global__ __launch_bounds__(768) void gather_kernel(
    const float* __restrict__ dv, const float* __restrict__ regTok,
    float* __restrict__ out)
{
    int row = blockIdx.x * 4 + (threadIdx.x / 192);
    int t = threadIdx.x % 192;
    int b = row / (KEEP + 1), k = row % (KEEP + 1);
    const float* src = (k < KEEP)
        ? dv + ((size_t)b * NN + g_topk[b * KEEP + k]) * DD
        : regTok;
    float4 v = ((const float4*)src)[t];
    ((float4*)(out + (size_t)row * DD))[t] = v;
}

extern "C" void kernel_launch(void* const* d_in, const int* in_sizes, int n_in,
                              void* d_out, int out_size)
{
    const float* dv   = (const float*)d_in[0];
    const float* text = (const float*)d_in[1];
    const float* W1   = (const float*)d_in[2];
    const float* b1   = (const float*)d_in[3];
    const float* W2   = (const float*)d_in[4];
    const float* b2   = (const float*)d_in[5];
    const float* regT = (const float*)d_in[6];
    float* out = (float*)d_out;
    (void)in_sizes; (void)n_in;

    static int smem_set = 0;
    if (!smem_set) {
        cudaFuncSetAttribute(scorer_approx, cudaFuncAttributeMaxDynamicSharedMemorySize, SA_BYTES);
        cudaFuncSetAttribute(refine_mma,    cudaFuncAttributeMaxDynamicSharedMemorySize, RF_BYTES);
        smem_set = 1;
    }

    prepare_kernel<<<DD * HH / 256 + BB, 256>>>(W1, text, b1);
    scorer_approx<<<MM / 128, 256, SA_BYTES>>>(dv, W2, b2);
    topk128_kernel<<<BB, 1024>>>();
    refine_mma<<<BB * 4, 256, RF_BYTES>>>(dv, W2);

    const int visElems = BB * (KEEP + 1) * DD;
    int writeIdx = (out_size >= visElems + BB * KEEP) ? 1 : 0;
    select_kernel<<<BB, 128>>>(b2, out + visElems, writeIdx);
    gather_kernel<<<BB * (KEEP + 1) / 4, 768>>>(dv, regT, out);
}

// round 14
// speedup vs baseline: 1.0205x; 1.0205x over previous
#include <cuda_runtime.h>
#include <cuda_bf16.h>
#include <cuda_fp16.h>
#include <math.h>
#include <stdint.h>

#define BB 64
#define NN 1024
#define SS 64
#define DD 768
#define HH 256
#define KEEP 96
#define CAND 128
#define MM (BB*NN)

// ---------------- device scratch (no allocations allowed) ----------------
__device__ float          g_ctxh[BB*HH];
__device__ float          g_scoresA[MM];
__device__ int            g_cand[BB*CAND];
__device__ int            g_topk[BB*KEEP];
__device__ float          g_rpart[2][BB*CAND];
__device__ unsigned       g_done[BB];               // refine completion tickets (mod-4 logic, no reset needed)
__device__ __nv_bfloat16  g_Bhi[HH*DD];             // refine: W1 visual, [h][d], bf16 hi
__device__ __nv_bfloat16  g_Blo[HH*DD];             // refine: bf16 lo residual
__device__ __half         g_Bh16[HH*DD];            // approx: W1 visual, [h][d], fp16

// ---------------- PTX helpers ----------------
__device__ __forceinline__ uint32_t smem_u32(const void* p) {
    uint32_t a;
    asm("{ .reg .u64 t; cvta.to.shared.u64 t, %1; cvt.u32.u64 %0, t; }" : "=r"(a) : "l"(p));
    return a;
}
__device__ __forceinline__ void ldsm4(uint32_t* r, uint32_t addr) {
    asm volatile("ldmatrix.sync.aligned.m8n8.x4.shared.b16 {%0,%1,%2,%3}, [%4];"
                 : "=r"(r[0]), "=r"(r[1]), "=r"(r[2]), "=r"(r[3]) : "r"(addr));
}
__device__ __forceinline__ void mma_bf16(float* d, const uint32_t* a, const uint32_t* b) {
    asm volatile(
        "mma.sync.aligned.m16n8k16.row.col.f32.bf16.bf16.f32 "
        "{%0,%1,%2,%3}, {%4,%5,%6,%7}, {%8,%9}, {%0,%1,%2,%3};"
        : "+f"(d[0]), "+f"(d[1]), "+f"(d[2]), "+f"(d[3])
        : "r"(a[0]), "r"(a[1]), "r"(a[2]), "r"(a[3]), "r"(b[0]), "r"(b[1]));
}
// fp16 inputs, fp16 accumulate (packed f16x2 x2)
__device__ __forceinline__ void mma_f16acc(uint32_t* d, const uint32_t* a, const uint32_t* b) {
    asm volatile(
        "mma.sync.aligned.m16n8k16.row.col.f16.f16.f16.f16 "
        "{%0,%1}, {%2,%3,%4,%5}, {%6,%7}, {%0,%1};"
        : "+r"(d[0]), "+r"(d[1])
        : "r"(a[0]), "r"(a[1]), "r"(a[2]), "r"(a[3]), "r"(b[0]), "r"(b[1]));
}
__device__ __forceinline__ void cpasync16(uint32_t dst, const void* src) {
    asm volatile("cp.async.ca.shared.global [%0], [%1], 16;" :: "r"(dst), "l"(src));
}
__device__ __forceinline__ void cpasync_commit() { asm volatile("cp.async.commit_group;"); }
__device__ __forceinline__ void cpasync_wait0()  { asm volatile("cp.async.wait_group 0;"); }

__device__ __forceinline__ void split_bf16(float x, uint32_t& hi_us, uint32_t& lo_us) {
    __nv_bfloat16 h = __float2bfloat16_rn(x);
    float r = x - __bfloat162float(h);
    __nv_bfloat16 l = __float2bfloat16_rn(r);
    hi_us = (uint32_t)__bfloat16_as_ushort(h);
    lo_us = (uint32_t)__bfloat16_as_ushort(l);
}
__device__ __forceinline__ uint32_t f2_to_h2(float x, float y) {
    __half2 h = __floats2half2_rn(x, y);
    return *(uint32_t*)&h;
}

// ---------------- Kernel 0: fused prep (W1 splits) + ctx ----------------
__global__ __launch_bounds__(256) void prepare_kernel(
    const float* __restrict__ W1, const float* __restrict__ text,
    const float* __restrict__ b1)
{
    if (blockIdx.x < DD * HH / 256) {
        int e = blockIdx.x * 256 + threadIdx.x;
        int d = e >> 8, h = e & 255;
        float x = W1[(size_t)d * HH + h];
        uint32_t hi, lo; split_bf16(x, hi, lo);
        g_Bhi[h * DD + d] = __ushort_as_bfloat16((unsigned short)hi);
        g_Blo[h * DD + d] = __ushort_as_bfloat16((unsigned short)lo);
        g_Bh16[h * DD + d] = __float2half_rn(x);
        return;
    }
    __shared__ float tm[DD];
    int b = blockIdx.x - DD * HH / 256, tid = threadIdx.x;
    for (int d = tid; d < DD; d += 256) {
        const float* p = text + (size_t)b * SS * DD + d;
        float s = 0.f;
        #pragma unroll 8
        for (int j = 0; j < SS; ++j) s += p[(size_t)j * DD];
        tm[d] = s * (1.0f / SS);
    }
    __syncthreads();
    int h = tid;
    float acc = b1[h];
    const float* w = W1 + (size_t)DD * HH + h;
    #pragma unroll 8
    for (int d = 0; d < DD; ++d) acc += tm[d] * w[(size_t)d * HH];
    g_ctxh[b * HH + h] = acc;
}

// ================= Approx scorer: fp16/f16acc, 8 warps, warp tile 32x64 =================
// (R12 configuration — best measured. Block 256 thr 2Mx4N, tile 64x256, K-chunks 64.)
#define SA_A(buf)  ((uint32_t)((buf)*9216))
#define SA_B(buf)  ((uint32_t)(18432 + (buf)*36864))
#define SA_CTX 92160u
#define SA_W2  93184u
#define SA_PART 94208u
#define SA_BYTES 95232u

__global__ __launch_bounds__(256, 2) void scorer_approx(
    const float* __restrict__ dv, const float* __restrict__ W2,
    const float* __restrict__ b2p)
{
    extern __shared__ char smem[];
    uint32_t sb = smem_u32(smem);
    const int tid = threadIdx.x, wid = tid >> 5, lane = tid & 31;
    const int warpM = wid >> 2, warpN = wid & 3;
    const int row0 = blockIdx.x * 64;
    const int b = blockIdx.x >> 4;

    ((float*)(smem + SA_CTX))[tid] = g_ctxh[b * HH + tid];
    ((float*)(smem + SA_W2))[tid]  = W2[tid];

    uint32_t acc2[2][8][2];
    #pragma unroll
    for (int m = 0; m < 2; ++m)
        #pragma unroll
        for (int j = 0; j < 8; ++j) { acc2[m][j][0] = 0u; acc2[m][j][1] = 0u; }

    const uint32_t a_row_l = (uint32_t)(lane & 15);
    const uint32_t a_k_l   = (uint32_t)(lane >> 4) * 16u;
    const uint32_t b_n_l   = (uint32_t)((lane & 7) + ((lane >> 4) << 3));
    const uint32_t b_k_l   = (uint32_t)((lane >> 3) & 1) * 16u;

    const int ar = tid >> 4, ac = tid & 15;
    const float* aG = dv + (size_t)(row0 + ar) * DD + ac * 4;
    const uint32_t aSt = (uint32_t)(ar * 144 + ac * 8);

    { // chunk 0
        #pragma unroll
        for (int i = 0; i < 4; ++i) {
            float4 v = *(const float4*)(aG + (size_t)i * 16 * DD);
            uint2 hv = { f2_to_h2(v.x, v.y), f2_to_h2(v.z, v.w) };
            *(uint2*)(smem + SA_A(0) + aSt + i * 16 * 144) = hv;
        }
        #pragma unroll
        for (int i = 0; i < 8; ++i) {
            int idx = i * 256 + tid;
            int n = idx >> 3, q = idx & 7;
            cpasync16(sb + SA_B(0) + n*144 + q*16, g_Bh16 + (size_t)n * DD + q * 8);
        }
        cpasync_commit();
        cpasync_wait0();
    }
    __syncthreads();

    for (int c = 0; c < 12; ++c) {
        const int cur = c & 1, nxt = cur ^ 1;
        float4 v[4];
        if (c < 11) {
            const int k0 = (c + 1) * 64;
            #pragma unroll
            for (int i = 0; i < 8; ++i) {
                int idx = i * 256 + tid;
                int n = idx >> 3, q = idx & 7;
                cpasync16(sb + SA_B(nxt) + n*144 + q*16, g_Bh16 + (size_t)n * DD + k0 + q * 8);
            }
            cpasync_commit();
            #pragma unroll
            for (int i = 0; i < 4; ++i)
                v[i] = *(const float4*)(aG + k0 + (size_t)i * 16 * DD);
        }

        const uint32_t Ah = sb + SA_A(cur), Bh = sb + SA_B(cur);
        #pragma unroll
        for (int kk = 0; kk < 4; ++kk) {
            const uint32_t kb = (uint32_t)(kk * 32);
            uint32_t ah[2][4];
            #pragma unroll
            for (int mt = 0; mt < 2; ++mt)
                ldsm4(ah[mt], Ah + (uint32_t)(warpM*32 + mt*16 + a_row_l)*144 + kb + a_k_l);
            #pragma unroll
            for (int nt = 0; nt < 4; ++nt) {
                uint32_t bh[4];
                ldsm4(bh, Bh + (uint32_t)(warpN*64 + nt*16 + b_n_l)*144 + kb + b_k_l);
                #pragma unroll
                for (int mt = 0; mt < 2; ++mt) {
                    mma_f16acc(acc2[mt][nt*2],   ah[mt], bh);
                    mma_f16acc(acc2[mt][nt*2+1], ah[mt], bh+2);
                }
            }
        }

        if (c < 11) {
            #pragma unroll
            for (int i = 0; i < 4; ++i) {
                uint2 hv = { f2_to_h2(v[i].x, v[i].y), f2_to_h2(v[i].z, v[i].w) };
                *(uint2*)(smem + SA_A(nxt) + aSt + i * 16 * 144) = hv;
            }
            cpasync_wait0();
        }
        __syncthreads();
    }

    const float* sctx = (const float*)(smem + SA_CTX);
    const float* sw2  = (const float*)(smem + SA_W2);
    float* part = (float*)(smem + SA_PART);
    #pragma unroll
    for (int mt = 0; mt < 2; ++mt) {
        float lg0 = 0.f, lg1 = 0.f;
        #pragma unroll
        for (int j = 0; j < 8; ++j) {
            int n = warpN*64 + j*8 + (lane & 3)*2;
            float c0 = sctx[n], c1 = sctx[n+1], w0 = sw2[n], w1 = sw2[n+1];
            float2 f01 = __half22float2(*(__half2*)&acc2[mt][j][0]);
            float2 f23 = __half22float2(*(__half2*)&acc2[mt][j][1]);
            lg0 += fmaxf(f01.x + c0, 0.f) * w0 + fmaxf(f01.y + c1, 0.f) * w1;
            lg1 += fmaxf(f23.x + c0, 0.f) * w0 + fmaxf(f23.y + c1, 0.f) * w1;
        }
        lg0 += __shfl_xor_sync(0xffffffffu, lg0, 1);
        lg0 += __shfl_xor_sync(0xffffffffu, lg0, 2);
        lg1 += __shfl_xor_sync(0xffffffffu, lg1, 1);
        lg1 += __shfl_xor_sync(0xffffffffu, lg1, 2);
        if ((lane & 3) == 0) {
            int r0 = warpM*32 + mt*16 + (lane >> 2);
            part[r0 * 4 + warpN]       = lg0;
            part[(r0 + 8) * 4 + warpN] = lg1;
        }
    }
    __syncthreads();
    if (tid < 64)
        g_scoresA[row0 + tid] = part[tid*4] + part[tid*4+1] + part[tid*4+2] + part[tid*4+3] + b2p[0];
}

// ---------------- approx top-128: 16-bit binary search ----------------
__global__ __launch_bounds__(1024) void topk128_kernel()
{
    __shared__ int weq[32], wsel[32];
    int b = blockIdx.x, i = threadIdx.x;
    int lane = i & 31, warp = i >> 5;
    unsigned bits = __float_as_uint(g_scoresA[b * NN + i]);
    unsigned ui = (bits & 0x80000000u) ? ~bits : (bits | 0x80000000u);
    ui &= 0xFFFF0000u;                    // coarse 16-bit key; ties -> index order

    unsigned thr = 0;
    #pragma unroll
    for (int bit = 31; bit >= 16; --bit) {
        unsigned trial = thr | (1u << bit);
        int c = __syncthreads_count(ui >= trial);
        if (c >= CAND) thr = trial;
    }
    int isGT = ui > thr;
    int isEQ = (ui == thr);
    int cntGT = __syncthreads_count(isGT);
    int k2 = CAND - cntGT;

    unsigned lmlt = (lane == 0) ? 0u : (0xffffffffu >> (32 - lane));
    unsigned eqm = __ballot_sync(0xffffffffu, isEQ);
    if (lane == 0) weq[warp] = __popc(eqm);
    __syncthreads();
    int eqBefore = __popc(eqm & lmlt);
    #pragma unroll
    for (int w = 0; w < 32; ++w) if (w < warp) eqBefore += weq[w];

    int flag = isGT || (isEQ && eqBefore < k2);
    unsigned sm_ = __ballot_sync(0xffffffffu, flag);
    if (lane == 0) wsel[warp] = __popc(sm_);
    __syncthreads();
    int pos = __popc(sm_ & lmlt);
    #pragma unroll
    for (int w = 0; w < 32; ++w) if (w < warp) pos += wsel[w];

    if (flag) g_cand[b * CAND + pos] = i;
}

// ================= Refine: 3-term bf16 (R10 config) + fused exact select =================
#define RF_A(buf, term) ((uint32_t)(((buf)*2 + (term)) * 5120))
#define RF_B(buf, term) ((uint32_t)(20480 + ((buf)*2 + (term)) * 10240))
#define RF_CTX  61440u
#define RF_W2   61952u
#define RF_PART 62464u
#define RF_BYTES 63488u

__global__ __launch_bounds__(256, 2) void refine_mma(
    const float* __restrict__ dv, const float* __restrict__ W2,
    const float* __restrict__ b2p, float* outIdxF, int writeIdx)
{
    extern __shared__ char smem[];
    uint32_t sb = smem_u32(smem);
    const int tid = threadIdx.x, wid = tid >> 5, lane = tid & 31;
    const int warpM = wid >> 2, warpN = wid & 3;
    const int batch = blockIdx.x >> 2;
    const int half  = (blockIdx.x >> 1) & 1;
    const int nHalf = blockIdx.x & 1;

    if (tid < 128) {
        ((float*)(smem + RF_CTX))[tid] = g_ctxh[batch * HH + nHalf * 128 + tid];
        ((float*)(smem + RF_W2))[tid]  = W2[nHalf * 128 + tid];
    }

    float acc[2][4][4];
    #pragma unroll
    for (int m = 0; m < 2; ++m)
        #pragma unroll
        for (int j = 0; j < 4; ++j)
            #pragma unroll
            for (int r = 0; r < 4; ++r) acc[m][j][r] = 0.f;

    const uint32_t a_row_l = (uint32_t)(lane & 15);
    const uint32_t a_k_l   = (uint32_t)(lane >> 4) * 16u;
    const uint32_t b_n_l   = (uint32_t)((lane & 7) + ((lane >> 4) << 3));
    const uint32_t b_k_l   = (uint32_t)((lane >> 3) & 1) * 16u;

    const int ar0 = tid >> 3, aq0 = tid & 7;
    const int ar1 = (tid + 256) >> 3, aq1 = tid & 7;
    const int crow0 = g_cand[batch * CAND + half * 64 + ar0];
    const int crow1 = g_cand[batch * CAND + half * 64 + ar1];
    const float* aG0 = dv + ((size_t)batch * NN + crow0) * DD + aq0 * 4;
    const float* aG1 = dv + ((size_t)batch * NN + crow1) * DD + aq1 * 4;
    const uint32_t aSt0 = (uint32_t)(ar0 * 80 + aq0 * 8);
    const uint32_t aSt1 = (uint32_t)(ar1 * 80 + aq1 * 8);
    const __nv_bfloat16* BsrcH = g_Bhi + (size_t)nHalf * 128 * DD;
    const __nv_bfloat16* BsrcL = g_Blo + (size_t)nHalf * 128 * DD;

    {
        #pragma unroll
        for (int u = 0; u < 2; ++u) {
            float4 v = u ? *(const float4*)aG1 : *(const float4*)aG0;
            uint32_t h0,h1,h2,h3,l0,l1,l2,l3;
            split_bf16(v.x,h0,l0); split_bf16(v.y,h1,l1);
            split_bf16(v.z,h2,l2); split_bf16(v.w,h3,l3);
            uint2 hv = { h0 | (h1<<16), h2 | (h3<<16) };
            uint2 lv = { l0 | (l1<<16), l2 | (l3<<16) };
            uint32_t st = u ? aSt1 : aSt0;
            *(uint2*)(smem + RF_A(0,0) + st) = hv;
            *(uint2*)(smem + RF_A(0,1) + st) = lv;
        }
        #pragma unroll
        for (int i = 0; i < 4; ++i) {
            int idx = i * 256 + tid;
            int kq = idx & 3, n = (idx >> 2) & 127, term = idx >> 9;
            const __nv_bfloat16* src = (term ? BsrcL : BsrcH) + (size_t)n * DD + kq * 8;
            cpasync16(sb + RF_B(0, term) + n*80 + kq*16, src);
        }
        cpasync_commit();
        cpasync_wait0();
    }
    __syncthreads();

    for (int c = 0; c < 24; ++c) {
        const int cur = c & 1, nxt = cur ^ 1;
        float4 v0, v1;
        if (c < 23) {
            const int k0 = (c + 1) * 32;
            #pragma unroll
            for (int i = 0; i < 4; ++i) {
                int idx = i * 256 + tid;
                int kq = idx & 3, n = (idx >> 2) & 127, term = idx >> 9;
                const __nv_bfloat16* src = (term ? BsrcL : BsrcH) + (size_t)n * DD + k0 + kq * 8;
                cpasync16(sb + RF_B(nxt, term) + n*80 + kq*16, src);
            }
            cpasync_commit();
            v0 = *(const float4*)(aG0 + k0);
            v1 = *(const float4*)(aG1 + k0);
        }

        const uint32_t Ah = sb + RF_A(cur,0), Al = sb + RF_A(cur,1);
        const uint32_t Bh = sb + RF_B(cur,0), Bl = sb + RF_B(cur,1);
        #pragma unroll
        for (int kk = 0; kk < 2; ++kk) {
            const uint32_t kb = (uint32_t)(kk * 32);
            uint32_t ah[2][4], al[2][4];
            #pragma unroll
            for (int mt = 0; mt < 2; ++mt) {
                const uint32_t aoff = (uint32_t)(warpM*32 + mt*16 + a_row_l)*80 + kb + a_k_l;
                ldsm4(ah[mt], Ah + aoff);
                ldsm4(al[mt], Al + aoff);
            }
            #pragma unroll
            for (int nt = 0; nt < 2; ++nt) {
                uint32_t bh[4], bl[4];
                const uint32_t boff = (uint32_t)(warpN*32 + nt*16 + b_n_l)*80 + kb + b_k_l;
                ldsm4(bh, Bh + boff);
                ldsm4(bl, Bl + boff);
                #pragma unroll
                for (int mt = 0; mt < 2; ++mt) {
                    float* d0 = acc[mt][nt*2], *d1 = acc[mt][nt*2+1];
                    mma_bf16(d0, ah[mt], bh);   mma_bf16(d1, ah[mt], bh+2);
                    mma_bf16(d0, ah[mt], bl);   mma_bf16(d1, ah[mt], bl+2);
                    mma_bf16(d0, al[mt], bh);   mma_bf16(d1, al[mt], bh+2);
                }
            }
        }

        if (c < 23) {
            #pragma unroll
            for (int u = 0; u < 2; ++u) {
                float4 v = u ? v1 : v0;
                uint32_t h0,h1,h2,h3,l0,l1,l2,l3;
                split_bf16(v.x,h0,l0); split_bf16(v.y,h1,l1);
                split_bf16(v.z,h2,l2); split_bf16(v.w,h3,l3);
                uint2 hv = { h0 | (h1<<16), h2 | (h3<<16) };
                uint2 lv = { l0 | (l1<<16), l2 | (l3<<16) };
                uint32_t st = u ? aSt1 : aSt0;
                *(uint2*)(smem + RF_A(nxt,0) + st) = hv;
                *(uint2*)(smem + RF_A(nxt,1) + st) = lv;
            }
            cpasync_wait0();
        }
        __syncthreads();
    }

    const float* sctx = (const float*)(smem + RF_CTX);
    const float* sw2  = (const float*)(smem + RF_W2);
    float* part = (float*)(smem + RF_PART);
    #pragma unroll
    for (int mt = 0; mt < 2; ++mt) {
        float lg0 = 0.f, lg1 = 0.f;
        #pragma unroll
        for (int j = 0; j < 4; ++j) {
            int cl = warpN*32 + j*8 + (lane & 3)*2;
            float c0 = sctx[cl], c1 = sctx[cl+1], w0 = sw2[cl], w1 = sw2[cl+1];
            lg0 += fmaxf(acc[mt][j][0] + c0, 0.f) * w0 + fmaxf(acc[mt][j][1] + c1, 0.f) * w1;
            lg1 += fmaxf(acc[mt][j][2] + c0, 0.f) * w0 + fmaxf(acc[mt][j][3] + c1, 0.f) * w1;
        }
        lg0 += __shfl_xor_sync(0xffffffffu, lg0, 1);
        lg0 += __shfl_xor_sync(0xffffffffu, lg0, 2);
        lg1 += __shfl_xor_sync(0xffffffffu, lg1, 1);
        lg1 += __shfl_xor_sync(0xffffffffu, lg1, 2);
        if ((lane & 3) == 0) {
            int r0 = warpM*32 + mt*16 + (lane >> 2);
            part[r0 * 4 + warpN]       = lg0;
            part[(r0 + 8) * 4 + warpN] = lg1;
        }
    }
    __syncthreads();
    if (tid < 64)
        g_rpart[nHalf][batch * CAND + half * 64 + tid] =
            part[tid*4] + part[tid*4+1] + part[tid*4+2] + part[tid*4+3];

    // ---- fused select: last of 4 blocks for this batch runs exact top-96 ----
    __threadfence();
    __shared__ int isLast;
    if (tid == 0) {
        unsigned old = atomicAdd(&g_done[batch], 1u);
        isLast = ((old & 3u) == 3u) ? 1 : 0;
    }
    __syncthreads();
    if (isLast) {
        __threadfence();                         // acquire: see all 4 blocks' rpart
        float* sc = (float*)(smem + RF_PART);    // reuse: 128 floats
        int* wsl = (int*)(smem + RF_PART + 512);
        float bias2 = b2p[0];
        if (tid < 128) {
            float lg = g_rpart[0][batch * CAND + tid] + g_rpart[1][batch * CAND + tid] + bias2;
            sc[tid] = 1.f / (1.f + expf(-lg));
        }
        __syncthreads();
        int flag = 0; unsigned m = 0;
        if (tid < 128) {
            float my = sc[tid];
            int rank = 0;
            #pragma unroll 4
            for (int j = 0; j < CAND; ++j) {
                float sj = sc[j];
                rank += (sj > my) || (sj == my && j < tid);
            }
            flag = (rank < KEEP);
            m = __ballot_sync(0xffffffffu, flag);
            if (lane == 0) wsl[tid >> 5] = __popc(m);
        }
        __syncthreads();
        if (tid < 128 && flag) {
            unsigned lmlt = (lane == 0) ? 0u : (0xffffffffu >> (32 - lane));
            int pos = __popc(m & lmlt);
            int wp = tid >> 5;
            #pragma unroll
            for (int w = 0; w < 4; ++w) if (w < wp) pos += wsl[w];
            int orig = g_cand[batch * CAND + tid];
            g_topk[batch * KEEP + pos] = orig;
            if (writeIdx) outIdxF[batch * KEEP + pos] = (float)orig;
        }
    }
}

// ---------------- gather: 4 rows per block ----------------
__global__ __launch_bounds__(768) void gather_kernel(
    const float* __restrict__ dv, const float* __restrict__ regTok,
    float* __restrict__ out)
{
    int row = blockIdx.x * 4 + (threadIdx.x / 192);
    int t = threadIdx.x % 192;
    int b = row / (KEEP + 1), k = row % (KEEP + 1);
    const float* src = (k < KEEP)
        ? dv + ((size_t)b * NN + g_topk[b * KEEP + k]) * DD
        : regTok;
    float4 v = ((const float4*)src)[t];
    ((float4*)(out + (size_t)row * DD))[t] = v;
}

extern "C" void kernel_launch(void* const* d_in, const int* in_sizes, int n_in,
                              void* d_out, int out_size)
{
    const float* dv   = (const float*)d_in[0];
    const float* text = (const float*)d_in[1];
    const float* W1   = (const float*)d_in[2];
    const float* b1   = (const float*)d_in[3];
    const float* W2   = (const float*)d_in[4];
    const float* b2   = (const float*)d_in[5];
    const float* regT = (const float*)d_in[6];
    float* out = (float*)d_out;
    (void)in_sizes; (void)n_in;

    static int smem_set = 0;
    if (!smem_set) {
        cudaFuncSetAttribute(scorer_approx, cudaFuncAttributeMaxDynamicSharedMemorySize, SA_BYTES);
        cudaFuncSetAttribute(refine_mma,    cudaFuncAttributeMaxDynamicSharedMemorySize, RF_BYTES);
        smem_set = 1;
    }

    const int visElems = BB * (KEEP + 1) * DD;
    int writeIdx = (out_size >= visElems + BB * KEEP) ? 1 : 0;

    prepare_kernel<<<DD * HH / 256 + BB, 256>>>(W1, text, b1);
    scorer_approx<<<MM / 64, 256, SA_BYTES>>>(dv, W2, b2);
    topk128_kernel<<<BB, 1024>>>();
    refine_mma<<<BB * 4, 256, RF_BYTES>>>(dv, W2, b2, out + visElems, writeIdx);
    gather_kernel<<<BB * (KEEP + 1) / 4, 768>>>(dv, regT, out);
}